// round 16
// baseline (speedup 1.0000x reference)
#include <cuda_runtime.h>
#include <math.h>

// ---------------- scratch (__device__ globals; no allocations) ----------------
__device__ float g_x0 [4*16*32*32];
__device__ float g_xa [4*4*64*64];
__device__ float g_xb [4*4*128*128];
__device__ float g_xc [4*4*256*256];

#define GSTRIDE 262144            // 512*512 guide plane stride

// ============================================================================
// lin: 1x1 conv (384->16) + bias + leaky. 64 blocks x 256 threads.
// ============================================================================
__global__ __launch_bounds__(256) void lin_kernel(
    const float* __restrict__ x, const float* __restrict__ lw,
    const float* __restrict__ lb, float* __restrict__ x0)
{
    __shared__ float sw[16*384];
    const int tid = threadIdx.x;
    for (int i = tid; i < 16*384; i += 256) sw[i] = lw[i];
    __syncthreads();
    const int pix = blockIdx.x*64 + (tid & 63);
    const int b   = pix >> 10;
    const int hw  = pix & 1023;
    const int o0  = (tid >> 6) * 4;
    const float* xp  = x + b*384*1024 + hw;
    const float* w0p = sw + (o0+0)*384;
    const float* w1p = sw + (o0+1)*384;
    const float* w2p = sw + (o0+2)*384;
    const float* w3p = sw + (o0+3)*384;
    float a0=0.f, a1=0.f, a2=0.f, a3=0.f;
    #pragma unroll 4
    for (int i = 0; i < 384; ++i) {
        float xv = xp[i*1024];
        a0 += w0p[i]*xv; a1 += w1p[i]*xv; a2 += w2p[i]*xv; a3 += w3p[i]*xv;
    }
    a0 += lb[o0+0]; a1 += lb[o0+1]; a2 += lb[o0+2]; a3 += lb[o0+3];
    a0 = (a0 >= 0.f) ? a0 : 0.01f*a0;
    a1 = (a1 >= 0.f) ? a1 : 0.01f*a1;
    a2 = (a2 >= 0.f) ? a2 : 0.01f*a2;
    a3 = (a3 >= 0.f) ? a3 : 0.01f*a3;
    float* op = x0 + (b*16 + o0)*1024 + hw;
    op[0] = a0; op[1024] = a1; op[2048] = a2; op[3072] = a3;
}

// ---- fused guide fetch: level pixel (gh,gw) at factor F from 512x512 src ----
template<int F>
__device__ __forceinline__ float4 fetch_guide(const float* __restrict__ gb,
                                              int gh, int gw, int H, int W)
{
    float4 v;
    if ((gh >= 0) & (gh < H) & (gw >= 0) & (gw < W)) {
        if (F == 1) {
            int off = gh*512 + gw;
            v.x = gb[off];
            v.y = gb[off + GSTRIDE];
            v.z = gb[off + 2*GSTRIDE];
        } else if (F == 2) {
            int off = (2*gh)*512 + 2*gw;
            float2 a0 = *(const float2*)(gb + off);
            float2 a1 = *(const float2*)(gb + off + 512);
            float2 b0 = *(const float2*)(gb + off + GSTRIDE);
            float2 b1 = *(const float2*)(gb + off + GSTRIDE + 512);
            float2 c0 = *(const float2*)(gb + off + 2*GSTRIDE);
            float2 c1 = *(const float2*)(gb + off + 2*GSTRIDE + 512);
            v.x = 0.25f*(a0.x + a0.y + a1.x + a1.y);
            v.y = 0.25f*(b0.x + b0.y + b1.x + b1.y);
            v.z = 0.25f*(c0.x + c0.y + c1.x + c1.y);
        } else if (F == 4) {
            int off = (4*gh + 1)*512 + 4*gw;
            float4 a0 = *(const float4*)(gb + off);
            float4 a1 = *(const float4*)(gb + off + 512);
            float4 b0 = *(const float4*)(gb + off + GSTRIDE);
            float4 b1 = *(const float4*)(gb + off + GSTRIDE + 512);
            float4 c0 = *(const float4*)(gb + off + 2*GSTRIDE);
            float4 c1 = *(const float4*)(gb + off + 2*GSTRIDE + 512);
            v.x = 0.25f*(a0.y + a0.z + a1.y + a1.z);
            v.y = 0.25f*(b0.y + b0.z + b1.y + b1.z);
            v.z = 0.25f*(c0.y + c0.z + c1.y + c1.z);
        } else {
            int off = (F*gh + (F>>1) - 1)*512 + (F*gw + (F>>1) - 1);
            v.x = 0.25f*(gb[off] + gb[off+1] + gb[off+512] + gb[off+513]);
            v.y = 0.25f*(gb[off+GSTRIDE] + gb[off+GSTRIDE+1] +
                         gb[off+GSTRIDE+512] + gb[off+GSTRIDE+513]);
            v.z = 0.25f*(gb[off+2*GSTRIDE] + gb[off+2*GSTRIDE+1] +
                         gb[off+2*GSTRIDE+512] + gb[off+2*GSTRIDE+513]);
        }
    } else {
        v.x = v.y = v.z = 1e19f;     // sentinel -> kern == 0 exactly
    }
    v.w = 0.f;
    return v;
}

// ============================================================================
// pac_tile: CI=16 stage (64x64 only), 256 threads, guide resize fused (F=8).
// ============================================================================
#define TW 32
#define TH 8
#define GP (TW+2)
#define GTILE ((TH+2)*GP)
#define XP (TW/2+2)
#define XTILE ((TH/2+2)*XP)

template<int CI, int CO, int F>
__global__ __launch_bounds__(256) void pac_tile(
    const float* __restrict__ xin, const float* __restrict__ guide,
    const float* __restrict__ wt, float* __restrict__ out,
    int H, int W)
{
    constexpr int NC4 = CI/4;
    __shared__ float4 sg[GTILE];
    __shared__ float4 sx[XTILE*NC4];
    __shared__ float4 swt[9*CO*NC4];

    const int tid = threadIdx.x;
    const int b   = blockIdx.z;
    const int h0  = blockIdx.y * TH;
    const int w0  = blockIdx.x * TW;
    const int HW  = H*W;
    const int H2 = H >> 1, W2 = W >> 1, HW2 = H2*W2;

    const float* gb = guide + b*3*GSTRIDE;
    for (int i = tid; i < GTILE; i += 256) {
        int r = i / GP, q = i - r*GP;
        sg[i] = fetch_guide<F>(gb, h0 - 1 + r, w0 - 1 + q, H, W);
    }
    const float* xb = xin + b*CI*HW2;
    for (int i = tid; i < XTILE*NC4; i += 256) {
        int pos = i / NC4, c4 = i - pos*NC4;
        int r = pos / XP, q = pos - r*XP;
        int xh = (h0>>1) - 1 + r, xw = (w0>>1) - 1 + q;
        float4 v = make_float4(0.f, 0.f, 0.f, 0.f);
        if ((xh >= 0) & (xh < H2) & (xw >= 0) & (xw < W2)) {
            int off = xh*W2 + xw;
            const float* p = xb + (c4*4)*HW2 + off;
            v.x = p[0]; v.y = p[HW2]; v.z = p[2*HW2]; v.w = p[3*HW2];
        }
        sx[i] = v;
    }
    for (int i = tid; i < 9*CO*NC4; i += 256) {
        int c4 = i % NC4;
        int t2 = i / NC4;
        int o  = t2 % CO;
        int k  = t2 / CO;
        float4 v;
        v.x = wt[(o*CI + c4*4 + 0)*9 + k];
        v.y = wt[(o*CI + c4*4 + 1)*9 + k];
        v.z = wt[(o*CI + c4*4 + 2)*9 + k];
        v.w = wt[(o*CI + c4*4 + 3)*9 + k];
        swt[i] = v;
    }
    __syncthreads();

    const int ty = tid >> 5, tx = tid & 31;
    const int gi0 = (ty+1)*GP + (tx+1);
    const float4 gc = sg[gi0];

    float acc[CO];
    #pragma unroll
    for (int o = 0; o < CO; ++o) acc[o] = 0.f;

    #pragma unroll
    for (int k = 0; k < 9; ++k) {
        const int di = k/3 - 1, dj = k%3 - 1;
        float4 g4 = sg[gi0 + di*GP + dj];
        float d0 = g4.x - gc.x, d1 = g4.y - gc.y, d2 = g4.z - gc.z;
        float kern = __expf(-0.5f*(d0*d0 + d1*d1 + d2*d2));
        const int xo = ((((ty+di)>>1)+1)*XP + (((tx+dj)>>1)+1)) * NC4;
        #pragma unroll
        for (int o = 0; o < CO; ++o) {
            float s = 0.f;
            #pragma unroll
            for (int c4 = 0; c4 < NC4; ++c4) {
                float4 xv = sx[xo + c4];
                float4 wv = swt[(k*CO + o)*NC4 + c4];
                s += wv.x*xv.x + wv.y*xv.y + wv.z*xv.z + wv.w*xv.w;
            }
            acc[o] += kern * s;
        }
    }
    const int h = h0 + ty, w = w0 + tx;
    #pragma unroll
    for (int o = 0; o < CO; ++o) {
        float v = acc[o];
        v = (v >= 0.f) ? v : 0.01f*v;
        out[(b*CO + o)*HW + h*W + w] = v;
    }
}

// ============================================================================
// pac_pair: generic CI=4 mid stage (used for 128^2, F=4). 128 threads,
// 1x2 pairs, tile 32x8. (R11 champion version.)
// ============================================================================
#define PTW 32
#define PTH 8
#define PGP (PTW+2)            // 34
#define PGT ((PTH+2)*PGP)      // 340
#define PXP (PTW/2+2)          // 18
#define PXT ((PTH/2+2)*PXP)    // 108

template<int CO, int ACT, int F>
__global__ __launch_bounds__(128) void pac_pair(
    const float* __restrict__ xin,
    const float* __restrict__ guide,
    const float* __restrict__ wt,
    float* __restrict__ out,
    int H, int W)
{
    __shared__ float4 sg[PGT];
    __shared__ float4 sx[PXT];
    __shared__ float4 swt[9*4];

    const int tid = threadIdx.x;
    const int b   = blockIdx.z;
    const int h0  = blockIdx.y * PTH;
    const int w0  = blockIdx.x * PTW;
    const int HW  = H*W;
    const int H2 = H >> 1, W2 = W >> 1, HW2 = H2*W2;

    const float* gb = guide + b*3*GSTRIDE;
    for (int i = tid; i < PGT; i += 128) {
        int r = i / PGP, q = i - r*PGP;
        sg[i] = fetch_guide<F>(gb, h0 - 1 + r, w0 - 1 + q, H, W);
    }
    const float* xb = xin + b*4*HW2;
    for (int i = tid; i < PXT; i += 128) {
        int r = i / PXP, q = i - r*PXP;
        int xh = (h0>>1) - 1 + r, xw = (w0>>1) - 1 + q;
        float4 v = make_float4(0.f, 0.f, 0.f, 0.f);
        if ((xh >= 0) & (xh < H2) & (xw >= 0) & (xw < W2)) {
            int off = xh*W2 + xw;
            const float* p = xb + off;
            v.x = p[0]; v.y = p[HW2]; v.z = p[2*HW2]; v.w = p[3*HW2];
        }
        sx[i] = v;
    }
    if (tid < 36) {
        int ci = tid & 3, k = tid >> 2;
        float4 v;
        v.x = wt[(0*4 + ci)*9 + k];
        v.y = wt[(1*4 + ci)*9 + k];
        v.z = wt[(2*4 + ci)*9 + k];
        v.w = wt[(3*4 + ci)*9 + k];
        swt[k*4 + ci] = v;
    }
    __syncthreads();

    const int ty = tid >> 4;
    const int tx = tid & 15;

    const int rb = ((ty-1)>>1) + 1;
    float4 xw[2][3];
    #pragma unroll
    for (int rr = 0; rr < 2; ++rr)
        #pragma unroll
        for (int cc = 0; cc < 3; ++cc)
            xw[rr][cc] = sx[(rb+rr)*PXP + (tx+cc)];
    const int midrow = 1 - (ty & 1);
    float4 xmid[3];
    #pragma unroll
    for (int cc = 0; cc < 3; ++cc) xmid[cc] = xw[midrow][cc];

    const int gi0 = (ty+1)*PGP + (2*tx+1);
    const float4 gq0 = sg[gi0];
    const float4 gq1 = sg[gi0 + 1];

    float4 acc4[2];
    acc4[0] = make_float4(0.f,0.f,0.f,0.f);
    acc4[1] = make_float4(0.f,0.f,0.f,0.f);

    #pragma unroll
    for (int k = 0; k < 9; ++k) {
        const int di = k/3 - 1, dj = k%3 - 1;
        float4 xv0, xv1;
        {
            const int cs0 = ((0+dj) >> 1) + 1;
            const int cs1 = ((1+dj) >> 1) + 1;
            if (di == -1)      { xv0 = xw[0][cs0]; xv1 = xw[0][cs1]; }
            else if (di == 1)  { xv0 = xw[1][cs0]; xv1 = xw[1][cs1]; }
            else               { xv0 = xmid[cs0];  xv1 = xmid[cs1];  }
        }
        float4 g0 = sg[gi0 + di*PGP + dj];
        float4 g1 = sg[gi0 + 1 + di*PGP + dj];
        float e0 = g0.x - gq0.x, e1 = g0.y - gq0.y, e2 = g0.z - gq0.z;
        float f0 = g1.x - gq1.x, f1 = g1.y - gq1.y, f2 = g1.z - gq1.z;
        float kern0 = __expf(-0.5f*(e0*e0 + e1*e1 + e2*e2));
        float kern1 = __expf(-0.5f*(f0*f0 + f1*f1 + f2*f2));

        float4 wv0 = swt[k*4+0], wv1 = swt[k*4+1], wv2 = swt[k*4+2], wv3 = swt[k*4+3];
        acc4[0].x += kern0*(xv0.x*wv0.x + xv0.y*wv1.x + xv0.z*wv2.x + xv0.w*wv3.x);
        acc4[0].y += kern0*(xv0.x*wv0.y + xv0.y*wv1.y + xv0.z*wv2.y + xv0.w*wv3.y);
        acc4[0].z += kern0*(xv0.x*wv0.z + xv0.y*wv1.z + xv0.z*wv2.z + xv0.w*wv3.z);
        acc4[0].w += kern0*(xv0.x*wv0.w + xv0.y*wv1.w + xv0.z*wv2.w + xv0.w*wv3.w);
        acc4[1].x += kern1*(xv1.x*wv0.x + xv1.y*wv1.x + xv1.z*wv2.x + xv1.w*wv3.x);
        acc4[1].y += kern1*(xv1.x*wv0.y + xv1.y*wv1.y + xv1.z*wv2.y + xv1.w*wv3.y);
        acc4[1].z += kern1*(xv1.x*wv0.z + xv1.y*wv1.z + xv1.z*wv2.z + xv1.w*wv3.z);
        acc4[1].w += kern1*(xv1.x*wv0.w + xv1.y*wv1.w + xv1.z*wv2.w + xv1.w*wv3.w);
    }

    const int h = h0 + ty, w = w0 + 2*tx;
    float* op = out + b*4*HW + h*W + w;
    #pragma unroll
    for (int p = 0; p < 2; ++p) {
        acc4[p].x = (acc4[p].x >= 0.f) ? acc4[p].x : 0.01f*acc4[p].x;
        acc4[p].y = (acc4[p].y >= 0.f) ? acc4[p].y : 0.01f*acc4[p].y;
        acc4[p].z = (acc4[p].z >= 0.f) ? acc4[p].z : 0.01f*acc4[p].z;
        acc4[p].w = (acc4[p].w >= 0.f) ? acc4[p].w : 0.01f*acc4[p].w;
    }
    *(float2*)(op)        = make_float2(acc4[0].x, acc4[1].x);
    *(float2*)(op + HW)   = make_float2(acc4[0].y, acc4[1].y);
    *(float2*)(op + 2*HW) = make_float2(acc4[0].z, acc4[1].z);
    *(float2*)(op + 3*HW) = make_float2(acc4[0].w, acc4[1].w);
}

// ============================================================================
// pac_pair2: 256^2 stage (F=2, CO=4, leaky). Scalar-plane guide smem with
// vectorized interior staging; EDGE-SYMMETRIC exp kernels (E,S,SE,SW computed
// once per tile position -> each tap is one scalar LDS; center tap == 1).
// ============================================================================
#define P2RS 36               // plane row stride; level col q -> idx q+1
#define P2PL (10*P2RS)        // 360 floats per plane
#define P2ET (9*34)           // edge rows 0..8

#define SG2(ch, r, q) sgp2[(ch)*P2PL + (r)*P2RS + (q) + 1]

__global__ __launch_bounds__(128) void pac_pair2(
    const float* __restrict__ xin,    // (4,4,128,128)
    const float* __restrict__ guide,  // (4,3,512,512)
    const float* __restrict__ wt,     // (4,4,3,3)
    float* __restrict__ out,          // (4,4,256,256)
    int H, int W)                     // 256, 256
{
    __shared__ float  sgp2[3*P2PL];
    __shared__ float  kE[P2ET], kS[P2ET], kSE[P2ET], kSW[P2ET];
    __shared__ float4 sx[PXT];
    __shared__ float4 swt[9*4];

    const int tid = threadIdx.x;
    const int b   = blockIdx.z;
    const int h0  = blockIdx.y * PTH;
    const int w0  = blockIdx.x * PTW;
    const int HW  = H*W;
    const int H2 = H >> 1, W2 = W >> 1, HW2 = H2*W2;

    const float* gb = guide + b*3*GSTRIDE;

    const bool interior = (h0 >= 1) && (h0 + PTH + 1 <= H) &&
                          (w0 >= 1) && (w0 + PTW + 1 <= W);
    if (interior) {
        for (int i = tid; i < 3*10*16; i += 128) {
            int ch = i / 160;
            int rem = i - ch*160;
            int r = rem >> 4, j = rem & 15;
            const float* src = gb + ch*GSTRIDE + (2*(h0-1+r))*512 + 2*w0 + 4*j;
            float4 a = *(const float4*)src;
            float4 c = *(const float4*)(src + 512);
            float2 v = make_float2(0.25f*(a.x + a.y + c.x + c.y),
                                   0.25f*(a.z + a.w + c.z + c.w));
            *(float2*)&sgp2[ch*P2PL + r*P2RS + 2 + 2*j] = v;
        }
        if (tid < 60) {
            int ch = tid / 20;
            int rem = tid - ch*20;
            int r = rem >> 1, side = rem & 1;
            int gcol = side ? (2*w0 + 64) : (2*w0 - 2);
            const float* src = gb + ch*GSTRIDE + (2*(h0-1+r))*512 + gcol;
            float2 a = *(const float2*)src;
            float2 c = *(const float2*)(src + 512);
            sgp2[ch*P2PL + r*P2RS + (side ? 34 : 1)] =
                0.25f*(a.x + a.y + c.x + c.y);
        }
    } else {
        for (int i = tid; i < 340; i += 128) {
            int r = i / 34, q = i - r*34;
            float4 v = fetch_guide<2>(gb, h0 - 1 + r, w0 - 1 + q, H, W);
            int base = r*P2RS + q + 1;
            sgp2[base]          = v.x;
            sgp2[P2PL + base]   = v.y;
            sgp2[2*P2PL + base] = v.z;
        }
    }

    const float* xb = xin + b*4*HW2;
    for (int i = tid; i < PXT; i += 128) {
        int r = i / PXP, q = i - r*PXP;
        int xh = (h0>>1) - 1 + r, xw = (w0>>1) - 1 + q;
        float4 v = make_float4(0.f, 0.f, 0.f, 0.f);
        if ((xh >= 0) & (xh < H2) & (xw >= 0) & (xw < W2)) {
            int off = xh*W2 + xw;
            const float* p = xb + off;
            v.x = p[0]; v.y = p[HW2]; v.z = p[2*HW2]; v.w = p[3*HW2];
        }
        sx[i] = v;
    }
    if (tid < 36) {
        int ci = tid & 3, k = tid >> 2;
        float4 v;
        v.x = wt[(0*4 + ci)*9 + k];
        v.y = wt[(1*4 + ci)*9 + k];
        v.z = wt[(2*4 + ci)*9 + k];
        v.w = wt[(3*4 + ci)*9 + k];
        swt[k*4 + ci] = v;
    }
    __syncthreads();

    // ---- edge kernels (rows 0..8) ----
    for (int i = tid; i < P2ET; i += 128) {
        int r = i / 34, c = i - 34*r;
        int ce = (c < 33) ? c+1 : c;
        int cw = (c > 0)  ? c-1 : c;
        float c0 = SG2(0,r,c), c1 = SG2(1,r,c), c2 = SG2(2,r,c);
        float d0, d1, d2;
        d0 = SG2(0,r,ce)-c0;   d1 = SG2(1,r,ce)-c1;   d2 = SG2(2,r,ce)-c2;
        kE[i]  = __expf(-0.5f*(d0*d0 + d1*d1 + d2*d2));
        d0 = SG2(0,r+1,c)-c0;  d1 = SG2(1,r+1,c)-c1;  d2 = SG2(2,r+1,c)-c2;
        kS[i]  = __expf(-0.5f*(d0*d0 + d1*d1 + d2*d2));
        d0 = SG2(0,r+1,ce)-c0; d1 = SG2(1,r+1,ce)-c1; d2 = SG2(2,r+1,ce)-c2;
        kSE[i] = __expf(-0.5f*(d0*d0 + d1*d1 + d2*d2));
        d0 = SG2(0,r+1,cw)-c0; d1 = SG2(1,r+1,cw)-c1; d2 = SG2(2,r+1,cw)-c2;
        kSW[i] = __expf(-0.5f*(d0*d0 + d1*d1 + d2*d2));
    }
    __syncthreads();

    const int ty = tid >> 4;          // 0..7
    const int tx = tid & 15;          // pair; pixel cols 2*tx, 2*tx+1

    const int rb = ((ty-1)>>1) + 1;
    float4 xw[2][3];
    #pragma unroll
    for (int rr = 0; rr < 2; ++rr)
        #pragma unroll
        for (int cc = 0; cc < 3; ++cc)
            xw[rr][cc] = sx[(rb+rr)*PXP + (tx+cc)];
    const int midrow = 1 - (ty & 1);
    float4 xmid[3];
    #pragma unroll
    for (int cc = 0; cc < 3; ++cc) xmid[cc] = xw[midrow][cc];

    // tap kernels via edge lookups. center (R,C): R=ty+1, C0=2tx+1, C1=2tx+2
    const int R = ty + 1, C0 = 2*tx + 1;
    const int eU = (R-1)*34, eR = R*34;   // row bases
    float kn0[9], kn1[9];
    kn0[0] = kSE[eU + C0-1]; kn0[1] = kS[eU + C0];  kn0[2] = kSW[eU + C0+1];
    kn0[3] = kE [eR + C0-1]; kn0[4] = 1.f;          kn0[5] = kE [eR + C0];
    kn0[6] = kSW[eR + C0];   kn0[7] = kS[eR + C0];  kn0[8] = kSE[eR + C0];
    kn1[0] = kSE[eU + C0];   kn1[1] = kS[eU + C0+1];kn1[2] = kSW[eU + C0+2];
    kn1[3] = kE [eR + C0];   kn1[4] = 1.f;          kn1[5] = kE [eR + C0+1];
    kn1[6] = kSW[eR + C0+1]; kn1[7] = kS[eR + C0+1];kn1[8] = kSE[eR + C0+1];

    float4 acc4[2];
    acc4[0] = make_float4(0.f,0.f,0.f,0.f);
    acc4[1] = make_float4(0.f,0.f,0.f,0.f);

    #pragma unroll
    for (int k = 0; k < 9; ++k) {
        const int di = k/3 - 1, dj = k%3 - 1;
        float4 xv0, xv1;
        {
            const int cs0 = ((0+dj) >> 1) + 1;
            const int cs1 = ((1+dj) >> 1) + 1;
            if (di == -1)      { xv0 = xw[0][cs0]; xv1 = xw[0][cs1]; }
            else if (di == 1)  { xv0 = xw[1][cs0]; xv1 = xw[1][cs1]; }
            else               { xv0 = xmid[cs0];  xv1 = xmid[cs1];  }
        }
        const float kern0 = kn0[k], kern1 = kn1[k];
        float4 wv0 = swt[k*4+0], wv1 = swt[k*4+1], wv2 = swt[k*4+2], wv3 = swt[k*4+3];
        acc4[0].x += kern0*(xv0.x*wv0.x + xv0.y*wv1.x + xv0.z*wv2.x + xv0.w*wv3.x);
        acc4[0].y += kern0*(xv0.x*wv0.y + xv0.y*wv1.y + xv0.z*wv2.y + xv0.w*wv3.y);
        acc4[0].z += kern0*(xv0.x*wv0.z + xv0.y*wv1.z + xv0.z*wv2.z + xv0.w*wv3.z);
        acc4[0].w += kern0*(xv0.x*wv0.w + xv0.y*wv1.w + xv0.z*wv2.w + xv0.w*wv3.w);
        acc4[1].x += kern1*(xv1.x*wv0.x + xv1.y*wv1.x + xv1.z*wv2.x + xv1.w*wv3.x);
        acc4[1].y += kern1*(xv1.x*wv0.y + xv1.y*wv1.y + xv1.z*wv2.y + xv1.w*wv3.y);
        acc4[1].z += kern1*(xv1.x*wv0.z + xv1.y*wv1.z + xv1.z*wv2.z + xv1.w*wv3.z);
        acc4[1].w += kern1*(xv1.x*wv0.w + xv1.y*wv1.w + xv1.z*wv2.w + xv1.w*wv3.w);
    }

    const int h = h0 + ty, w = w0 + 2*tx;
    float* op = out + b*4*HW + h*W + w;
    #pragma unroll
    for (int p = 0; p < 2; ++p) {
        acc4[p].x = (acc4[p].x >= 0.f) ? acc4[p].x : 0.01f*acc4[p].x;
        acc4[p].y = (acc4[p].y >= 0.f) ? acc4[p].y : 0.01f*acc4[p].y;
        acc4[p].z = (acc4[p].z >= 0.f) ? acc4[p].z : 0.01f*acc4[p].z;
        acc4[p].w = (acc4[p].w >= 0.f) ? acc4[p].w : 0.01f*acc4[p].w;
    }
    *(float2*)(op)        = make_float2(acc4[0].x, acc4[1].x);
    *(float2*)(op + HW)   = make_float2(acc4[0].y, acc4[1].y);
    *(float2*)(op + 2*HW) = make_float2(acc4[0].z, acc4[1].z);
    *(float2*)(op + 3*HW) = make_float2(acc4[0].w, acc4[1].w);
}

// ============================================================================
// pac_quad512: 512^2 final stage (CO=1, sigmoid, F=1). 128 threads; 2x2 quads.
// Scalar-plane guide smem + vectorized interior staging + EDGE-SYMMETRIC exps.
// ============================================================================
#define QTW 32
#define QTH 16
#define QGR (QTH+2)            // 18 rows
#define QRS 40                 // padded row stride (floats); body cols at idx 4
#define QPL (QGR*QRS)          // 720 floats per plane
#define QET (17*34)            // edge rows 0..16
#define QXP (QTW/2+2)          // 18
#define QXT ((QTH/2+2)*QXP)    // 180

#define SGv(ch, r, c) sgp[(ch)*QPL + (r)*QRS + (c) + 3]

__global__ __launch_bounds__(128) void pac_quad512(
    const float* __restrict__ xin,
    const float* __restrict__ guide,
    const float* __restrict__ wt,
    float* __restrict__ out,
    int H, int W)
{
    __shared__ float  sgp[3*QPL];
    __shared__ float  kE[QET], kS[QET], kSE[QET], kSW[QET];
    __shared__ float4 sx[QXT];

    const int tid = threadIdx.x;
    const int b   = blockIdx.z;
    const int h0  = blockIdx.y * QTH;
    const int w0  = blockIdx.x * QTW;
    const int HW  = H*W;
    const int H2 = H >> 1, W2 = W >> 1, HW2 = H2*W2;

    const float* gb = guide + b*3*GSTRIDE;

    const bool interior = (h0 >= 1) && (h0 + QTH + 1 <= H) &&
                          (w0 >= 1) && (w0 + QTW + 1 <= W);
    if (interior) {
        #pragma unroll 2
        for (int i = tid; i < 3*QGR*8; i += 128) {
            int ch = i / (QGR*8);
            int rem = i - ch*(QGR*8);
            int r = rem >> 3, g = rem & 7;
            float4 v = *(const float4*)(gb + ch*GSTRIDE + (h0-1+r)*512 + w0 + 4*g);
            *(float4*)&sgp[ch*QPL + r*QRS + 4 + 4*g] = v;
        }
        if (tid < 3*QGR*2) {
            int ch = tid / (QGR*2);
            int rem = tid - ch*(QGR*2);
            int r = rem >> 1, side = rem & 1;
            int gcol = side ? (w0 + QTW) : (w0 - 1);
            int sidx = side ? (QTW + 4) : 3;
            sgp[ch*QPL + r*QRS + sidx] = gb[ch*GSTRIDE + (h0-1+r)*512 + gcol];
        }
    } else {
        for (int i = tid; i < QGR*34; i += 128) {
            int r = i / 34, q = i - r*34;
            int gh = h0 - 1 + r, gw = w0 - 1 + q;
            int base = r*QRS + q + 3;
            if ((gh >= 0) & (gh < H) & (gw >= 0) & (gw < W)) {
                int off = gh*512 + gw;
                sgp[base]         = gb[off];
                sgp[QPL + base]   = gb[GSTRIDE + off];
                sgp[2*QPL + base] = gb[2*GSTRIDE + off];
            } else {
                sgp[base] = 1e19f; sgp[QPL + base] = 1e19f; sgp[2*QPL + base] = 1e19f;
            }
        }
    }

    const float* xb = xin + b*4*HW2;
    for (int i = tid; i < QXT; i += 128) {
        int r = i / QXP, q = i - r*QXP;
        int xh = (h0>>1) - 1 + r, xw = (w0>>1) - 1 + q;
        float4 v = make_float4(0.f, 0.f, 0.f, 0.f);
        if ((xh >= 0) & (xh < H2) & (xw >= 0) & (xw < W2)) {
            int off = xh*W2 + xw;
            const float* p = xb + off;
            v.x = p[0]; v.y = p[HW2]; v.z = p[2*HW2]; v.w = p[3*HW2];
        }
        sx[i] = v;
    }
    float4 wr[9];
    #pragma unroll
    for (int k = 0; k < 9; ++k) {
        float4 v;
        v.x = __ldg(wt + 0*9 + k);
        v.y = __ldg(wt + 1*9 + k);
        v.z = __ldg(wt + 2*9 + k);
        v.w = __ldg(wt + 3*9 + k);
        wr[k] = v;
    }
    __syncthreads();

    // ---- edge kernels (rows 0..16) ----
    for (int i = tid; i < QET; i += 128) {
        int r = i / 34, c = i - 34*r;
        int ce = (c < 33) ? c+1 : c;
        int cw = (c > 0)  ? c-1 : c;
        float c0 = SGv(0,r,c), c1 = SGv(1,r,c), c2 = SGv(2,r,c);
        float d0, d1, d2;
        d0 = SGv(0,r,ce)-c0;   d1 = SGv(1,r,ce)-c1;   d2 = SGv(2,r,ce)-c2;
        kE[i]  = __expf(-0.5f*(d0*d0 + d1*d1 + d2*d2));
        d0 = SGv(0,r+1,c)-c0;  d1 = SGv(1,r+1,c)-c1;  d2 = SGv(2,r+1,c)-c2;
        kS[i]  = __expf(-0.5f*(d0*d0 + d1*d1 + d2*d2));
        d0 = SGv(0,r+1,ce)-c0; d1 = SGv(1,r+1,ce)-c1; d2 = SGv(2,r+1,ce)-c2;
        kSE[i] = __expf(-0.5f*(d0*d0 + d1*d1 + d2*d2));
        d0 = SGv(0,r+1,cw)-c0; d1 = SGv(1,r+1,cw)-c1; d2 = SGv(2,r+1,cw)-c2;
        kSW[i] = __expf(-0.5f*(d0*d0 + d1*d1 + d2*d2));
    }
    __syncthreads();

    const int qy = tid >> 4;
    const int qx = tid & 15;

    float4 xw[9];
    #pragma unroll
    for (int rr = 0; rr < 3; ++rr)
        #pragma unroll
        for (int cc = 0; cc < 3; ++cc)
            xw[rr*3+cc] = sx[(qy+rr)*QXP + (qx+cc)];

    float acc1[4] = {0.f, 0.f, 0.f, 0.f};

    #pragma unroll
    for (int p = 0; p < 4; ++p) {
        const int rr = p >> 1, cc = p & 1;
        const int R = 2*qy + 1 + rr, C = 2*qx + 1 + cc;
        const int eU = (R-1)*34 + C, eR = R*34 + C;
        float kn[9];
        kn[0] = kSE[eU - 1]; kn[1] = kS[eU];  kn[2] = kSW[eU + 1];
        kn[3] = kE [eR - 1]; kn[4] = 1.f;     kn[5] = kE [eR];
        kn[6] = kSW[eR];     kn[7] = kS[eR];  kn[8] = kSE[eR];
        float a = 0.f;
        #pragma unroll
        for (int k = 0; k < 9; ++k) {
            const int di = k/3 - 1, dj = k%3 - 1;
            const int xr = (rr + di + 2) >> 1;
            const int xc = (cc + dj + 2) >> 1;
            float4 xv = xw[xr*3 + xc];
            float4 wv = wr[k];
            a += kn[k]*(xv.x*wv.x + xv.y*wv.y + xv.z*wv.z + xv.w*wv.w);
        }
        acc1[p] = a;
    }

    const int h = h0 + 2*qy, w = w0 + 2*qx;
    #pragma unroll
    for (int p = 0; p < 4; ++p)
        acc1[p] = 1.0f / (1.0f + __expf(-acc1[p]));
    float* op = out + b*HW + h*W + w;
    *(float2*)(op)     = make_float2(acc1[0], acc1[1]);
    *(float2*)(op + W) = make_float2(acc1[2], acc1[3]);
}

// ---------------- launch ----------------
extern "C" void kernel_launch(void* const* d_in, const int* in_sizes, int n_in,
                              void* d_out, int out_size)
{
    const float* x     = (const float*)d_in[0];
    const float* guide = (const float*)d_in[1];
    const float* lin_w = (const float*)d_in[2];
    const float* lin_b = (const float*)d_in[3];
    const float* w0    = (const float*)d_in[4];
    const float* w1    = (const float*)d_in[5];
    const float* w2    = (const float*)d_in[6];
    const float* w3    = (const float*)d_in[7];
    float* out = (float*)d_out;

    float *x0, *xa, *xb, *xc;
    cudaGetSymbolAddress((void**)&x0, g_x0);
    cudaGetSymbolAddress((void**)&xa, g_xa);
    cudaGetSymbolAddress((void**)&xb, g_xb);
    cudaGetSymbolAddress((void**)&xc, g_xc);

    lin_kernel<<<64, 256>>>(x, lin_w, lin_b, x0);

    pac_tile<16,4,8><<<dim3( 2,  8, 4), 256>>>(x0, guide, w0, xa,  64,  64);
    pac_pair<4,1,4><<<dim3( 4, 16, 4), 128>>>(xa, guide, w1, xb, 128, 128);
    pac_pair2      <<<dim3( 8, 32, 4), 128>>>(xb, guide, w2, xc, 256, 256);
    pac_quad512    <<<dim3(16, 32, 4), 128>>>(xc, guide, w3, out, 512, 512);
}

// round 17
// speedup vs baseline: 1.3712x; 1.3712x over previous
#include <cuda_runtime.h>
#include <math.h>

// ---------------- scratch (__device__ globals; no allocations) ----------------
__device__ float g_x0p[8*4*16*32*32];   // lin partial sums (8 splits)
__device__ float g_x0 [4*16*32*32];
__device__ float g_xa [4*4*64*64];
__device__ float g_xb [4*4*128*128];
__device__ float g_xc [4*4*256*256];

#define GSTRIDE 262144            // 512*512 guide plane stride

// ============================================================================
// lin_split: 1x1 conv partials. grid (64, 8): blockIdx.y = channel split s,
// channels [s*48, s*48+48). 512 blocks total -> 8x parallelism vs old lin.
// ============================================================================
__global__ __launch_bounds__(256) void lin_split(
    const float* __restrict__ x, const float* __restrict__ lw,
    float* __restrict__ xp)
{
    __shared__ float sw[16*48];
    const int s   = blockIdx.y;
    const int tid = threadIdx.x;
    for (int i = tid; i < 16*48; i += 256) {
        int o = i / 48, c = i - o*48;
        sw[i] = lw[o*384 + s*48 + c];
    }
    __syncthreads();
    const int pix = blockIdx.x*64 + (tid & 63);
    const int b   = pix >> 10;
    const int hw  = pix & 1023;
    const int o0  = (tid >> 6) * 4;
    const float* xpt = x + b*384*1024 + (s*48)*1024 + hw;
    const float* w0p = sw + (o0+0)*48;
    const float* w1p = sw + (o0+1)*48;
    const float* w2p = sw + (o0+2)*48;
    const float* w3p = sw + (o0+3)*48;
    float a0=0.f, a1=0.f, a2=0.f, a3=0.f;
    #pragma unroll 16
    for (int i = 0; i < 48; ++i) {
        float xv = xpt[i*1024];
        a0 += w0p[i]*xv; a1 += w1p[i]*xv; a2 += w2p[i]*xv; a3 += w3p[i]*xv;
    }
    float* op = xp + s*65536 + (b*16 + o0)*1024 + hw;
    op[0] = a0; op[1024] = a1; op[2048] = a2; op[3072] = a3;
}

// lin_combine: sum 8 partials + bias + leaky -> x0. 128 blocks x 256 thr,
// float2 per thread.
__global__ __launch_bounds__(256) void lin_combine(
    const float* __restrict__ xp, const float* __restrict__ lb,
    float* __restrict__ x0)
{
    const int idx  = blockIdx.x*256 + threadIdx.x;   // 0..32767
    const int base = idx*2;
    const int ch   = (base >> 10) & 15;
    float2 acc = make_float2(0.f, 0.f);
    #pragma unroll
    for (int s = 0; s < 8; ++s) {
        float2 v = *(const float2*)(xp + s*65536 + base);
        acc.x += v.x; acc.y += v.y;
    }
    float bv = lb[ch];
    acc.x += bv; acc.y += bv;
    acc.x = (acc.x >= 0.f) ? acc.x : 0.01f*acc.x;
    acc.y = (acc.y >= 0.f) ? acc.y : 0.01f*acc.y;
    *(float2*)(x0 + base) = acc;
}

// ---- fused guide fetch: level pixel (gh,gw) at factor F from 512x512 src ----
template<int F>
__device__ __forceinline__ float4 fetch_guide(const float* __restrict__ gb,
                                              int gh, int gw, int H, int W)
{
    float4 v;
    if ((gh >= 0) & (gh < H) & (gw >= 0) & (gw < W)) {
        if (F == 1) {
            int off = gh*512 + gw;
            v.x = gb[off];
            v.y = gb[off + GSTRIDE];
            v.z = gb[off + 2*GSTRIDE];
        } else if (F == 2) {
            int off = (2*gh)*512 + 2*gw;
            float2 a0 = *(const float2*)(gb + off);
            float2 a1 = *(const float2*)(gb + off + 512);
            float2 b0 = *(const float2*)(gb + off + GSTRIDE);
            float2 b1 = *(const float2*)(gb + off + GSTRIDE + 512);
            float2 c0 = *(const float2*)(gb + off + 2*GSTRIDE);
            float2 c1 = *(const float2*)(gb + off + 2*GSTRIDE + 512);
            v.x = 0.25f*(a0.x + a0.y + a1.x + a1.y);
            v.y = 0.25f*(b0.x + b0.y + b1.x + b1.y);
            v.z = 0.25f*(c0.x + c0.y + c1.x + c1.y);
        } else if (F == 4) {
            int off = (4*gh + 1)*512 + 4*gw;
            float4 a0 = *(const float4*)(gb + off);
            float4 a1 = *(const float4*)(gb + off + 512);
            float4 b0 = *(const float4*)(gb + off + GSTRIDE);
            float4 b1 = *(const float4*)(gb + off + GSTRIDE + 512);
            float4 c0 = *(const float4*)(gb + off + 2*GSTRIDE);
            float4 c1 = *(const float4*)(gb + off + 2*GSTRIDE + 512);
            v.x = 0.25f*(a0.y + a0.z + a1.y + a1.z);
            v.y = 0.25f*(b0.y + b0.z + b1.y + b1.z);
            v.z = 0.25f*(c0.y + c0.z + c1.y + c1.z);
        } else {
            int off = (F*gh + (F>>1) - 1)*512 + (F*gw + (F>>1) - 1);
            v.x = 0.25f*(gb[off] + gb[off+1] + gb[off+512] + gb[off+513]);
            v.y = 0.25f*(gb[off+GSTRIDE] + gb[off+GSTRIDE+1] +
                         gb[off+GSTRIDE+512] + gb[off+GSTRIDE+513]);
            v.z = 0.25f*(gb[off+2*GSTRIDE] + gb[off+2*GSTRIDE+1] +
                         gb[off+2*GSTRIDE+512] + gb[off+2*GSTRIDE+513]);
        }
    } else {
        v.x = v.y = v.z = 1e19f;     // sentinel -> kern == 0 exactly
    }
    v.w = 0.f;
    return v;
}

// ============================================================================
// pac_tile: CI=16 stage (64x64 only), 256 threads, guide resize fused (F=8).
// ============================================================================
#define TW 32
#define TH 8
#define GP (TW+2)
#define GTILE ((TH+2)*GP)
#define XP (TW/2+2)
#define XTILE ((TH/2+2)*XP)

template<int CI, int CO, int F>
__global__ __launch_bounds__(256) void pac_tile(
    const float* __restrict__ xin, const float* __restrict__ guide,
    const float* __restrict__ wt, float* __restrict__ out,
    int H, int W)
{
    constexpr int NC4 = CI/4;
    __shared__ float4 sg[GTILE];
    __shared__ float4 sx[XTILE*NC4];
    __shared__ float4 swt[9*CO*NC4];

    const int tid = threadIdx.x;
    const int b   = blockIdx.z;
    const int h0  = blockIdx.y * TH;
    const int w0  = blockIdx.x * TW;
    const int HW  = H*W;
    const int H2 = H >> 1, W2 = W >> 1, HW2 = H2*W2;

    const float* gb = guide + b*3*GSTRIDE;
    for (int i = tid; i < GTILE; i += 256) {
        int r = i / GP, q = i - r*GP;
        sg[i] = fetch_guide<F>(gb, h0 - 1 + r, w0 - 1 + q, H, W);
    }
    const float* xb = xin + b*CI*HW2;
    for (int i = tid; i < XTILE*NC4; i += 256) {
        int pos = i / NC4, c4 = i - pos*NC4;
        int r = pos / XP, q = pos - r*XP;
        int xh = (h0>>1) - 1 + r, xw = (w0>>1) - 1 + q;
        float4 v = make_float4(0.f, 0.f, 0.f, 0.f);
        if ((xh >= 0) & (xh < H2) & (xw >= 0) & (xw < W2)) {
            int off = xh*W2 + xw;
            const float* p = xb + (c4*4)*HW2 + off;
            v.x = p[0]; v.y = p[HW2]; v.z = p[2*HW2]; v.w = p[3*HW2];
        }
        sx[i] = v;
    }
    for (int i = tid; i < 9*CO*NC4; i += 256) {
        int c4 = i % NC4;
        int t2 = i / NC4;
        int o  = t2 % CO;
        int k  = t2 / CO;
        float4 v;
        v.x = wt[(o*CI + c4*4 + 0)*9 + k];
        v.y = wt[(o*CI + c4*4 + 1)*9 + k];
        v.z = wt[(o*CI + c4*4 + 2)*9 + k];
        v.w = wt[(o*CI + c4*4 + 3)*9 + k];
        swt[i] = v;
    }
    __syncthreads();

    const int ty = tid >> 5, tx = tid & 31;
    const int gi0 = (ty+1)*GP + (tx+1);
    const float4 gc = sg[gi0];

    float acc[CO];
    #pragma unroll
    for (int o = 0; o < CO; ++o) acc[o] = 0.f;

    #pragma unroll
    for (int k = 0; k < 9; ++k) {
        const int di = k/3 - 1, dj = k%3 - 1;
        float4 g4 = sg[gi0 + di*GP + dj];
        float d0 = g4.x - gc.x, d1 = g4.y - gc.y, d2 = g4.z - gc.z;
        float kern = __expf(-0.5f*(d0*d0 + d1*d1 + d2*d2));
        const int xo = ((((ty+di)>>1)+1)*XP + (((tx+dj)>>1)+1)) * NC4;
        #pragma unroll
        for (int o = 0; o < CO; ++o) {
            float s = 0.f;
            #pragma unroll
            for (int c4 = 0; c4 < NC4; ++c4) {
                float4 xv = sx[xo + c4];
                float4 wv = swt[(k*CO + o)*NC4 + c4];
                s += wv.x*xv.x + wv.y*xv.y + wv.z*xv.z + wv.w*xv.w;
            }
            acc[o] += kern * s;
        }
    }
    const int h = h0 + ty, w = w0 + tx;
    #pragma unroll
    for (int o = 0; o < CO; ++o) {
        float v = acc[o];
        v = (v >= 0.f) ? v : 0.01f*v;
        out[(b*CO + o)*HW + h*W + w] = v;
    }
}

// ============================================================================
// pac_pair: generic CI=4 mid stage (used for 128^2, F=4). 128 threads,
// 1x2 pairs, tile 32x8.
// ============================================================================
#define PTW 32
#define PTH 8
#define PGP (PTW+2)            // 34
#define PGT ((PTH+2)*PGP)      // 340
#define PXP (PTW/2+2)          // 18
#define PXT ((PTH/2+2)*PXP)    // 108

template<int CO, int ACT, int F>
__global__ __launch_bounds__(128) void pac_pair(
    const float* __restrict__ xin,
    const float* __restrict__ guide,
    const float* __restrict__ wt,
    float* __restrict__ out,
    int H, int W)
{
    __shared__ float4 sg[PGT];
    __shared__ float4 sx[PXT];
    __shared__ float4 swt[9*4];

    const int tid = threadIdx.x;
    const int b   = blockIdx.z;
    const int h0  = blockIdx.y * PTH;
    const int w0  = blockIdx.x * PTW;
    const int HW  = H*W;
    const int H2 = H >> 1, W2 = W >> 1, HW2 = H2*W2;

    const float* gb = guide + b*3*GSTRIDE;
    for (int i = tid; i < PGT; i += 128) {
        int r = i / PGP, q = i - r*PGP;
        sg[i] = fetch_guide<F>(gb, h0 - 1 + r, w0 - 1 + q, H, W);
    }
    const float* xb = xin + b*4*HW2;
    for (int i = tid; i < PXT; i += 128) {
        int r = i / PXP, q = i - r*PXP;
        int xh = (h0>>1) - 1 + r, xw = (w0>>1) - 1 + q;
        float4 v = make_float4(0.f, 0.f, 0.f, 0.f);
        if ((xh >= 0) & (xh < H2) & (xw >= 0) & (xw < W2)) {
            int off = xh*W2 + xw;
            const float* p = xb + off;
            v.x = p[0]; v.y = p[HW2]; v.z = p[2*HW2]; v.w = p[3*HW2];
        }
        sx[i] = v;
    }
    if (tid < 36) {
        int ci = tid & 3, k = tid >> 2;
        float4 v;
        v.x = wt[(0*4 + ci)*9 + k];
        v.y = wt[(1*4 + ci)*9 + k];
        v.z = wt[(2*4 + ci)*9 + k];
        v.w = wt[(3*4 + ci)*9 + k];
        swt[k*4 + ci] = v;
    }
    __syncthreads();

    const int ty = tid >> 4;
    const int tx = tid & 15;

    const int rb = ((ty-1)>>1) + 1;
    float4 xw[2][3];
    #pragma unroll
    for (int rr = 0; rr < 2; ++rr)
        #pragma unroll
        for (int cc = 0; cc < 3; ++cc)
            xw[rr][cc] = sx[(rb+rr)*PXP + (tx+cc)];
    const int midrow = 1 - (ty & 1);
    float4 xmid[3];
    #pragma unroll
    for (int cc = 0; cc < 3; ++cc) xmid[cc] = xw[midrow][cc];

    const int gi0 = (ty+1)*PGP + (2*tx+1);
    const float4 gq0 = sg[gi0];
    const float4 gq1 = sg[gi0 + 1];

    float4 acc4[2];
    acc4[0] = make_float4(0.f,0.f,0.f,0.f);
    acc4[1] = make_float4(0.f,0.f,0.f,0.f);

    #pragma unroll
    for (int k = 0; k < 9; ++k) {
        const int di = k/3 - 1, dj = k%3 - 1;
        float4 xv0, xv1;
        {
            const int cs0 = ((0+dj) >> 1) + 1;
            const int cs1 = ((1+dj) >> 1) + 1;
            if (di == -1)      { xv0 = xw[0][cs0]; xv1 = xw[0][cs1]; }
            else if (di == 1)  { xv0 = xw[1][cs0]; xv1 = xw[1][cs1]; }
            else               { xv0 = xmid[cs0];  xv1 = xmid[cs1];  }
        }
        float4 g0 = sg[gi0 + di*PGP + dj];
        float4 g1 = sg[gi0 + 1 + di*PGP + dj];
        float e0 = g0.x - gq0.x, e1 = g0.y - gq0.y, e2 = g0.z - gq0.z;
        float f0 = g1.x - gq1.x, f1 = g1.y - gq1.y, f2 = g1.z - gq1.z;
        float kern0 = __expf(-0.5f*(e0*e0 + e1*e1 + e2*e2));
        float kern1 = __expf(-0.5f*(f0*f0 + f1*f1 + f2*f2));

        float4 wv0 = swt[k*4+0], wv1 = swt[k*4+1], wv2 = swt[k*4+2], wv3 = swt[k*4+3];
        acc4[0].x += kern0*(xv0.x*wv0.x + xv0.y*wv1.x + xv0.z*wv2.x + xv0.w*wv3.x);
        acc4[0].y += kern0*(xv0.x*wv0.y + xv0.y*wv1.y + xv0.z*wv2.y + xv0.w*wv3.y);
        acc4[0].z += kern0*(xv0.x*wv0.z + xv0.y*wv1.z + xv0.z*wv2.z + xv0.w*wv3.z);
        acc4[0].w += kern0*(xv0.x*wv0.w + xv0.y*wv1.w + xv0.z*wv2.w + xv0.w*wv3.w);
        acc4[1].x += kern1*(xv1.x*wv0.x + xv1.y*wv1.x + xv1.z*wv2.x + xv1.w*wv3.x);
        acc4[1].y += kern1*(xv1.x*wv0.y + xv1.y*wv1.y + xv1.z*wv2.y + xv1.w*wv3.y);
        acc4[1].z += kern1*(xv1.x*wv0.z + xv1.y*wv1.z + xv1.z*wv2.z + xv1.w*wv3.z);
        acc4[1].w += kern1*(xv1.x*wv0.w + xv1.y*wv1.w + xv1.z*wv2.w + xv1.w*wv3.w);
    }

    const int h = h0 + ty, w = w0 + 2*tx;
    float* op = out + b*4*HW + h*W + w;
    #pragma unroll
    for (int p = 0; p < 2; ++p) {
        acc4[p].x = (acc4[p].x >= 0.f) ? acc4[p].x : 0.01f*acc4[p].x;
        acc4[p].y = (acc4[p].y >= 0.f) ? acc4[p].y : 0.01f*acc4[p].y;
        acc4[p].z = (acc4[p].z >= 0.f) ? acc4[p].z : 0.01f*acc4[p].z;
        acc4[p].w = (acc4[p].w >= 0.f) ? acc4[p].w : 0.01f*acc4[p].w;
    }
    *(float2*)(op)        = make_float2(acc4[0].x, acc4[1].x);
    *(float2*)(op + HW)   = make_float2(acc4[0].y, acc4[1].y);
    *(float2*)(op + 2*HW) = make_float2(acc4[0].z, acc4[1].z);
    *(float2*)(op + 3*HW) = make_float2(acc4[0].w, acc4[1].w);
}

// ============================================================================
// pac_pair2: 256^2 stage (F=2, CO=4, leaky). Scalar-plane guide smem with
// vectorized interior staging (R14 champion version).
// ============================================================================
#define P2RS 36               // plane row stride; level col q -> idx q+1
#define P2PL (10*P2RS)        // 360 floats per plane

#define SG2(ch, r, q) sgp2[(ch)*P2PL + (r)*P2RS + (q) + 1]

__global__ __launch_bounds__(128) void pac_pair2(
    const float* __restrict__ xin,    // (4,4,128,128)
    const float* __restrict__ guide,  // (4,3,512,512)
    const float* __restrict__ wt,     // (4,4,3,3)
    float* __restrict__ out,          // (4,4,256,256)
    int H, int W)                     // 256, 256
{
    __shared__ float  sgp2[3*P2PL];
    __shared__ float4 sx[PXT];
    __shared__ float4 swt[9*4];

    const int tid = threadIdx.x;
    const int b   = blockIdx.z;
    const int h0  = blockIdx.y * PTH;
    const int w0  = blockIdx.x * PTW;
    const int HW  = H*W;
    const int H2 = H >> 1, W2 = W >> 1, HW2 = H2*W2;

    const float* gb = guide + b*3*GSTRIDE;

    const bool interior = (h0 >= 1) && (h0 + PTH + 1 <= H) &&
                          (w0 >= 1) && (w0 + PTW + 1 <= W);
    if (interior) {
        for (int i = tid; i < 3*10*16; i += 128) {
            int ch = i / 160;
            int rem = i - ch*160;
            int r = rem >> 4, j = rem & 15;
            const float* src = gb + ch*GSTRIDE + (2*(h0-1+r))*512 + 2*w0 + 4*j;
            float4 a = *(const float4*)src;
            float4 c = *(const float4*)(src + 512);
            float2 v = make_float2(0.25f*(a.x + a.y + c.x + c.y),
                                   0.25f*(a.z + a.w + c.z + c.w));
            *(float2*)&sgp2[ch*P2PL + r*P2RS + 2 + 2*j] = v;
        }
        if (tid < 60) {
            int ch = tid / 20;
            int rem = tid - ch*20;
            int r = rem >> 1, side = rem & 1;
            int gcol = side ? (2*w0 + 64) : (2*w0 - 2);
            const float* src = gb + ch*GSTRIDE + (2*(h0-1+r))*512 + gcol;
            float2 a = *(const float2*)src;
            float2 c = *(const float2*)(src + 512);
            sgp2[ch*P2PL + r*P2RS + (side ? 34 : 1)] =
                0.25f*(a.x + a.y + c.x + c.y);
        }
    } else {
        for (int i = tid; i < 340; i += 128) {
            int r = i / 34, q = i - r*34;
            float4 v = fetch_guide<2>(gb, h0 - 1 + r, w0 - 1 + q, H, W);
            int base = r*P2RS + q + 1;
            sgp2[base]          = v.x;
            sgp2[P2PL + base]   = v.y;
            sgp2[2*P2PL + base] = v.z;
        }
    }

    const float* xb = xin + b*4*HW2;
    for (int i = tid; i < PXT; i += 128) {
        int r = i / PXP, q = i - r*PXP;
        int xh = (h0>>1) - 1 + r, xw = (w0>>1) - 1 + q;
        float4 v = make_float4(0.f, 0.f, 0.f, 0.f);
        if ((xh >= 0) & (xh < H2) & (xw >= 0) & (xw < W2)) {
            int off = xh*W2 + xw;
            const float* p = xb + off;
            v.x = p[0]; v.y = p[HW2]; v.z = p[2*HW2]; v.w = p[3*HW2];
        }
        sx[i] = v;
    }
    if (tid < 36) {
        int ci = tid & 3, k = tid >> 2;
        float4 v;
        v.x = wt[(0*4 + ci)*9 + k];
        v.y = wt[(1*4 + ci)*9 + k];
        v.z = wt[(2*4 + ci)*9 + k];
        v.w = wt[(3*4 + ci)*9 + k];
        swt[k*4 + ci] = v;
    }
    __syncthreads();

    const int ty = tid >> 4;          // 0..7 output row
    const int tx = tid & 15;          // pair; pixel cols 2*tx, 2*tx+1

    const int rb = ((ty-1)>>1) + 1;
    float4 xw[2][3];
    #pragma unroll
    for (int rr = 0; rr < 2; ++rr)
        #pragma unroll
        for (int cc = 0; cc < 3; ++cc)
            xw[rr][cc] = sx[(rb+rr)*PXP + (tx+cc)];
    const int midrow = 1 - (ty & 1);
    float4 xmid[3];
    #pragma unroll
    for (int cc = 0; cc < 3; ++cc) xmid[cc] = xw[midrow][cc];

    const int gr0 = ty + 1;
    const int gc0 = 2*tx + 1, gc1 = 2*tx + 2;
    const float q00 = SG2(0, gr0, gc0), q01 = SG2(1, gr0, gc0), q02 = SG2(2, gr0, gc0);
    const float q10 = SG2(0, gr0, gc1), q11 = SG2(1, gr0, gc1), q12 = SG2(2, gr0, gc1);

    float4 acc4[2];
    acc4[0] = make_float4(0.f,0.f,0.f,0.f);
    acc4[1] = make_float4(0.f,0.f,0.f,0.f);

    #pragma unroll
    for (int k = 0; k < 9; ++k) {
        const int di = k/3 - 1, dj = k%3 - 1;
        float4 xv0, xv1;
        {
            const int cs0 = ((0+dj) >> 1) + 1;
            const int cs1 = ((1+dj) >> 1) + 1;
            if (di == -1)      { xv0 = xw[0][cs0]; xv1 = xw[0][cs1]; }
            else if (di == 1)  { xv0 = xw[1][cs0]; xv1 = xw[1][cs1]; }
            else               { xv0 = xmid[cs0];  xv1 = xmid[cs1];  }
        }
        const int gr = gr0 + di;
        float e0 = SG2(0, gr, gc0+dj) - q00;
        float e1 = SG2(1, gr, gc0+dj) - q01;
        float e2 = SG2(2, gr, gc0+dj) - q02;
        float f0 = SG2(0, gr, gc1+dj) - q10;
        float f1 = SG2(1, gr, gc1+dj) - q11;
        float f2 = SG2(2, gr, gc1+dj) - q12;
        float kern0 = __expf(-0.5f*(e0*e0 + e1*e1 + e2*e2));
        float kern1 = __expf(-0.5f*(f0*f0 + f1*f1 + f2*f2));

        float4 wv0 = swt[k*4+0], wv1 = swt[k*4+1], wv2 = swt[k*4+2], wv3 = swt[k*4+3];
        acc4[0].x += kern0*(xv0.x*wv0.x + xv0.y*wv1.x + xv0.z*wv2.x + xv0.w*wv3.x);
        acc4[0].y += kern0*(xv0.x*wv0.y + xv0.y*wv1.y + xv0.z*wv2.y + xv0.w*wv3.y);
        acc4[0].z += kern0*(xv0.x*wv0.z + xv0.y*wv1.z + xv0.z*wv2.z + xv0.w*wv3.z);
        acc4[0].w += kern0*(xv0.x*wv0.w + xv0.y*wv1.w + xv0.z*wv2.w + xv0.w*wv3.w);
        acc4[1].x += kern1*(xv1.x*wv0.x + xv1.y*wv1.x + xv1.z*wv2.x + xv1.w*wv3.x);
        acc4[1].y += kern1*(xv1.x*wv0.y + xv1.y*wv1.y + xv1.z*wv2.y + xv1.w*wv3.y);
        acc4[1].z += kern1*(xv1.x*wv0.z + xv1.y*wv1.z + xv1.z*wv2.z + xv1.w*wv3.z);
        acc4[1].w += kern1*(xv1.x*wv0.w + xv1.y*wv1.w + xv1.z*wv2.w + xv1.w*wv3.w);
    }

    const int h = h0 + ty, w = w0 + 2*tx;
    float* op = out + b*4*HW + h*W + w;
    #pragma unroll
    for (int p = 0; p < 2; ++p) {
        acc4[p].x = (acc4[p].x >= 0.f) ? acc4[p].x : 0.01f*acc4[p].x;
        acc4[p].y = (acc4[p].y >= 0.f) ? acc4[p].y : 0.01f*acc4[p].y;
        acc4[p].z = (acc4[p].z >= 0.f) ? acc4[p].z : 0.01f*acc4[p].z;
        acc4[p].w = (acc4[p].w >= 0.f) ? acc4[p].w : 0.01f*acc4[p].w;
    }
    *(float2*)(op)        = make_float2(acc4[0].x, acc4[1].x);
    *(float2*)(op + HW)   = make_float2(acc4[0].y, acc4[1].y);
    *(float2*)(op + 2*HW) = make_float2(acc4[0].z, acc4[1].z);
    *(float2*)(op + 3*HW) = make_float2(acc4[0].w, acc4[1].w);
}

// ============================================================================
// pac_quad512: 512^2 final stage (CO=1, sigmoid, F=1). 128 threads; 2x2 quads.
// Scalar-plane guide smem; vectorized interior staging (R14 champion).
// ============================================================================
#define QTW 32
#define QTH 16
#define QGR (QTH+2)            // 18 rows
#define QRS 40                 // padded row stride (floats); body cols at idx 4
#define QPL (QGR*QRS)          // 720 floats per plane
#define QXP (QTW/2+2)          // 18
#define QXT ((QTH/2+2)*QXP)    // 180

#define SGv(ch, r, c) sgp[(ch)*QPL + (r)*QRS + (c) + 3]

__global__ __launch_bounds__(128) void pac_quad512(
    const float* __restrict__ xin,
    const float* __restrict__ guide,
    const float* __restrict__ wt,
    float* __restrict__ out,
    int H, int W)
{
    __shared__ float  sgp[3*QPL];
    __shared__ float4 sx[QXT];

    const int tid = threadIdx.x;
    const int b   = blockIdx.z;
    const int h0  = blockIdx.y * QTH;
    const int w0  = blockIdx.x * QTW;
    const int HW  = H*W;
    const int H2 = H >> 1, W2 = W >> 1, HW2 = H2*W2;

    const float* gb = guide + b*3*GSTRIDE;

    const bool interior = (h0 >= 1) && (h0 + QTH + 1 <= H) &&
                          (w0 >= 1) && (w0 + QTW + 1 <= W);
    if (interior) {
        #pragma unroll 2
        for (int i = tid; i < 3*QGR*8; i += 128) {
            int ch = i / (QGR*8);
            int rem = i - ch*(QGR*8);
            int r = rem >> 3, g = rem & 7;
            float4 v = *(const float4*)(gb + ch*GSTRIDE + (h0-1+r)*512 + w0 + 4*g);
            *(float4*)&sgp[ch*QPL + r*QRS + 4 + 4*g] = v;
        }
        if (tid < 3*QGR*2) {
            int ch = tid / (QGR*2);
            int rem = tid - ch*(QGR*2);
            int r = rem >> 1, side = rem & 1;
            int gcol = side ? (w0 + QTW) : (w0 - 1);
            int sidx = side ? (QTW + 4) : 3;
            sgp[ch*QPL + r*QRS + sidx] = gb[ch*GSTRIDE + (h0-1+r)*512 + gcol];
        }
    } else {
        for (int i = tid; i < QGR*34; i += 128) {
            int r = i / 34, q = i - r*34;
            int gh = h0 - 1 + r, gw = w0 - 1 + q;
            int base = r*QRS + q + 3;
            if ((gh >= 0) & (gh < H) & (gw >= 0) & (gw < W)) {
                int off = gh*512 + gw;
                sgp[base]         = gb[off];
                sgp[QPL + base]   = gb[GSTRIDE + off];
                sgp[2*QPL + base] = gb[2*GSTRIDE + off];
            } else {
                sgp[base] = 1e19f; sgp[QPL + base] = 1e19f; sgp[2*QPL + base] = 1e19f;
            }
        }
    }

    const float* xb = xin + b*4*HW2;
    for (int i = tid; i < QXT; i += 128) {
        int r = i / QXP, q = i - r*QXP;
        int xh = (h0>>1) - 1 + r, xw = (w0>>1) - 1 + q;
        float4 v = make_float4(0.f, 0.f, 0.f, 0.f);
        if ((xh >= 0) & (xh < H2) & (xw >= 0) & (xw < W2)) {
            int off = xh*W2 + xw;
            const float* p = xb + off;
            v.x = p[0]; v.y = p[HW2]; v.z = p[2*HW2]; v.w = p[3*HW2];
        }
        sx[i] = v;
    }
    float4 wr[9];
    #pragma unroll
    for (int k = 0; k < 9; ++k) {
        float4 v;
        v.x = __ldg(wt + 0*9 + k);
        v.y = __ldg(wt + 1*9 + k);
        v.z = __ldg(wt + 2*9 + k);
        v.w = __ldg(wt + 3*9 + k);
        wr[k] = v;
    }
    __syncthreads();

    const int qy = tid >> 4;
    const int qx = tid & 15;

    float4 xw[9];
    #pragma unroll
    for (int rr = 0; rr < 3; ++rr)
        #pragma unroll
        for (int cc = 0; cc < 3; ++cc)
            xw[rr*3+cc] = sx[(qy+rr)*QXP + (qx+cc)];

    float gq0[4], gq1[4], gq2[4];
    #pragma unroll
    for (int p = 0; p < 4; ++p) {
        const int rr = p >> 1, cc = p & 1;
        const int gr = 2*qy + 1 + rr, gc = 2*qx + 1 + cc;
        gq0[p] = SGv(0, gr, gc);
        gq1[p] = SGv(1, gr, gc);
        gq2[p] = SGv(2, gr, gc);
    }

    float acc1[4] = {0.f, 0.f, 0.f, 0.f};

    #pragma unroll
    for (int k = 0; k < 9; ++k) {
        const int di = k/3 - 1, dj = k%3 - 1;
        float4 wv = wr[k];
        #pragma unroll
        for (int p = 0; p < 4; ++p) {
            const int rr = p >> 1, cc = p & 1;
            const int gr = 2*qy + 1 + rr + di, gc = 2*qx + 1 + cc + dj;
            float d0 = SGv(0, gr, gc) - gq0[p];
            float d1 = SGv(1, gr, gc) - gq1[p];
            float d2 = SGv(2, gr, gc) - gq2[p];
            float kern = __expf(-0.5f*(d0*d0 + d1*d1 + d2*d2));
            const int xr = (rr + di + 2) >> 1;
            const int xc = (cc + dj + 2) >> 1;
            float4 xv = xw[xr*3 + xc];
            acc1[p] += kern*(xv.x*wv.x + xv.y*wv.y + xv.z*wv.z + xv.w*wv.w);
        }
    }

    const int h = h0 + 2*qy, w = w0 + 2*qx;
    #pragma unroll
    for (int p = 0; p < 4; ++p)
        acc1[p] = 1.0f / (1.0f + __expf(-acc1[p]));
    float* op = out + b*HW + h*W + w;
    *(float2*)(op)     = make_float2(acc1[0], acc1[1]);
    *(float2*)(op + W) = make_float2(acc1[2], acc1[3]);
}

// ---------------- launch ----------------
extern "C" void kernel_launch(void* const* d_in, const int* in_sizes, int n_in,
                              void* d_out, int out_size)
{
    const float* x     = (const float*)d_in[0];
    const float* guide = (const float*)d_in[1];
    const float* lin_w = (const float*)d_in[2];
    const float* lin_b = (const float*)d_in[3];
    const float* w0    = (const float*)d_in[4];
    const float* w1    = (const float*)d_in[5];
    const float* w2    = (const float*)d_in[6];
    const float* w3    = (const float*)d_in[7];
    float* out = (float*)d_out;

    float *x0p, *x0, *xa, *xb, *xc;
    cudaGetSymbolAddress((void**)&x0p, g_x0p);
    cudaGetSymbolAddress((void**)&x0,  g_x0);
    cudaGetSymbolAddress((void**)&xa,  g_xa);
    cudaGetSymbolAddress((void**)&xb,  g_xb);
    cudaGetSymbolAddress((void**)&xc,  g_xc);

    lin_split  <<<dim3(64, 8), 256>>>(x, lin_w, x0p);
    lin_combine<<<128, 256>>>(x0p, lin_b, x0);

    pac_tile<16,4,8><<<dim3( 2,  8, 4), 256>>>(x0, guide, w0, xa,  64,  64);
    pac_pair<4,1,4><<<dim3( 4, 16, 4), 128>>>(xa, guide, w1, xb, 128, 128);
    pac_pair2      <<<dim3( 8, 32, 4), 128>>>(xb, guide, w2, xc, 256, 256);
    pac_quad512    <<<dim3(16, 32, 4), 128>>>(xc, guide, w3, out, 512, 512);
}